// round 5
// baseline (speedup 1.0000x reference)
#include <cuda_runtime.h>
#include <math.h>

// ---------------------------------------------------------------------------
// EGNN  B=4, N=10000, E=160000, D=128, OUT=64, L=4
// R3: packed fma.rn.f32x2 in both fused-MLP GEMM mainloops (2x fp32 rate).
// ---------------------------------------------------------------------------
#define BATCH    4
#define NNODES   10000
#define NEDGES   160000
#define DIM      128
#define OUTD     64
#define NLAYERS  4
#define NEG      0.01f

#define TM       128     // edges/nodes per CTA tile
#define TN       128     // output features
#define BK       32      // K chunk
#define PAD      4
#define NTHREADS 256
#define NPART    20      // mean partials (deterministic)

typedef unsigned long long u64;

// ------------------------- device scratch (no mallocs) ---------------------
__device__ float g_pos[BATCH * NNODES * 3];
__device__ float g_h[(size_t)BATCH * NNODES * DIM];
__device__ float g_aggr[(size_t)BATCH * NNODES * DIM];
__device__ float g_msg[(size_t)BATCH * NEDGES * DIM];
__device__ int   g_cnt[NNODES];
__device__ float g_recip[NNODES];
__device__ int   g_off[NNODES + 1];
__device__ int   g_cursor[NNODES];
__device__ int   g_perm[NEDGES];
__device__ float g_hpart[BATCH * NPART * DIM];

__device__ __forceinline__ float lrelu(float x) { return x > 0.f ? x : NEG * x; }

// ---- packed f32x2 helpers --------------------------------------------------
__device__ __forceinline__ u64 pack_dup(float x) {
    u64 r;
    asm("mov.b64 %0, {%1, %1};" : "=l"(r) : "f"(x));
    return r;
}
__device__ __forceinline__ void fma2(u64& acc, u64 a, u64 b) {
    asm("fma.rn.f32x2 %0, %1, %2, %0;" : "+l"(acc) : "l"(a), "l"(b));
}
__device__ __forceinline__ float2 unpack2(u64 v) {
    float2 f;
    asm("mov.b64 {%0, %1}, %2;" : "=f"(f.x), "=f"(f.y) : "l"(v));
    return f;
}

// ------------------------------ CSR build ----------------------------------
__global__ void k_zero_cnt() {
    int n = blockIdx.x * blockDim.x + threadIdx.x;
    if (n < NNODES) g_cnt[n] = 0;
}

__global__ void k_count(const int* __restrict__ col) {
    int e = blockIdx.x * blockDim.x + threadIdx.x;
    if (e < NEDGES) atomicAdd(&g_cnt[col[e]], 1);
}

// single-block inclusive scan over N=10000 (10 chunks of 1024)
__global__ void k_scan() {
    __shared__ int ss[1024];
    int tid = threadIdx.x;
    int running = 0;
    for (int c = 0; c < 10; ++c) {
        int n = c * 1024 + tid;
        int v = (n < NNODES) ? g_cnt[n] : 0;
        ss[tid] = v;
        __syncthreads();
        for (int d = 1; d < 1024; d <<= 1) {
            int t = (tid >= d) ? ss[tid - d] : 0;
            __syncthreads();
            ss[tid] += t;
            __syncthreads();
        }
        int incl = ss[tid];
        if (n < NNODES) {
            g_off[n + 1]  = running + incl;
            g_cursor[n]   = running + incl - v;   // exclusive prefix
            g_recip[n]    = 1.0f / fmaxf((float)v, 1.0f);
        }
        if (c == 0 && tid == 0) g_off[0] = 0;
        int tot = ss[1023];
        __syncthreads();      // all reads done before next chunk overwrites ss
        running += tot;
    }
}

__global__ void k_fill(const int* __restrict__ col) {
    int e = blockIdx.x * blockDim.x + threadIdx.x;
    if (e < NEDGES) {
        int p = atomicAdd(&g_cursor[col[e]], 1);
        g_perm[p] = e;
    }
}

// sort each node's edge list ascending -> deterministic summation order
__global__ void k_sort() {
    int n = blockIdx.x * blockDim.x + threadIdx.x;
    if (n >= NNODES) return;
    int s = g_off[n], t = g_off[n + 1];
    for (int i = s + 1; i < t; ++i) {
        int v = g_perm[i];
        int j = i - 1;
        while (j >= s && g_perm[j] > v) { g_perm[j + 1] = g_perm[j]; --j; }
        g_perm[j + 1] = v;
    }
}

// ------------------------------ init ---------------------------------------
__global__ void k_init_pos(const float* __restrict__ x) {
    int i = blockIdx.x * blockDim.x + threadIdx.x;
    if (i < BATCH * NNODES * 3) g_pos[i] = x[i];  // identical flat layout
}

__global__ void k_h0(const float* __restrict__ w0, const float* __restrict__ b0) {
    int i = blockIdx.x * blockDim.x + threadIdx.x;
    if (i >= BATCH * NNODES * DIM) return;
    int j  = i & (DIM - 1);
    int bn = i >> 7;
    const float* p = &g_pos[bn * 3];
    float v = b0[j] + p[0] * w0[j] + p[1] * w0[DIM + j] + p[2] * w0[2 * DIM + j];
    g_h[i] = lrelu(v);
}

// --------------------- fused 2-layer MLP GEMM kernel ------------------------
// EDGE=true : A row e = [h[row[e]], h[col[e]], dist_sq] (K=257, last col special)
//             out -> g_msg
// EDGE=false: A row n = [h[n], aggr[n]] (K=256), out -> g_h += lrelu(...)
// Tile: 128 rows x 128 cols, 256 threads, 8x8 per thread done as 4x8 packed
// f32x2 pairs over adjacent rows (fma.rn.f32x2). Hidden kept in SMEM
// feature-major; second GEMM fused.
template <bool EDGE>
__global__ void __launch_bounds__(NTHREADS)
mlp_kernel(const int* __restrict__ row, const int* __restrict__ col,
           const float* __restrict__ W1, const float* __restrict__ b1,
           const float* __restrict__ W2, const float* __restrict__ b2)
{
    extern __shared__ float smem[];
    float* As  = smem;                              // [BK][TM+PAD]
    float* Ws  = As + BK * (TM + PAD);              // [BK][TN]
    float* Hs  = Ws + BK * TN;                      // [TN][TM+PAD] feature-major
    float* dsq = Hs + TN * (TM + PAD);              // [TM]
    int*   nid = (int*)(dsq + TM);                  // [2*TM]

    const int b   = blockIdx.y;
    const int m0  = blockIdx.x * TM;
    const int tid = threadIdx.x;
    const int tx  = tid & 15;      // feature group
    const int ty  = tid >> 4;      // row group

    const float* hb = g_h    + (size_t)b * NNODES * DIM;
    const float* ab = g_aggr + (size_t)b * NNODES * DIM;

    if (EDGE) {
        for (int i = tid; i < TM; i += NTHREADS) {
            int e = m0 + i;
            int r = row[e], c = col[e];
            nid[i]      = r;
            nid[TM + i] = c;
            const float* pr = &g_pos[((size_t)b * NNODES + r) * 3];
            const float* pc = &g_pos[((size_t)b * NNODES + c) * 3];
            float dx = pr[0] - pc[0], dy = pr[1] - pc[1], dz = pr[2] - pc[2];
            dsq[i] = dx * dx + dy * dy + dz * dz;
        }
        __syncthreads();
    }

    // packed accumulators: acc2[i2][j] holds rows (2*i2, 2*i2+1), column j
    u64 acc2[4][8];
#pragma unroll
    for (int i = 0; i < 4; ++i)
#pragma unroll
        for (int j = 0; j < 8; ++j) acc2[i][j] = 0ULL;

    // ---------------- GEMM 1: K = 256 (8 chunks); +dsq column for EDGE ------
#pragma unroll 1
    for (int kc = 0; kc < 8; ++kc) {
        const int k0 = kc * BK;
        // gathered A tile (k-major in SMEM)
        for (int s = tid; s < TM * 8; s += NTHREADS) {
            int ei = s >> 3, q = s & 7;
            const float* src;
            if (EDGE) {
                int node = (kc < 4) ? nid[ei] : nid[TM + ei];
                int kh   = (kc < 4) ? k0 : (k0 - DIM);
                src = hb + (size_t)node * DIM + kh + q * 4;
            } else {
                int node = m0 + ei;
                if (node >= NNODES) node = NNODES - 1;
                src = (kc < 4) ? (hb + (size_t)node * DIM + k0 + q * 4)
                               : (ab + (size_t)node * DIM + (k0 - DIM) + q * 4);
            }
            float4 v = *(const float4*)src;
            float* dst = &As[(q * 4) * (TM + PAD) + ei];
            dst[0]              = v.x;
            dst[TM + PAD]       = v.y;
            dst[2 * (TM + PAD)] = v.z;
            dst[3 * (TM + PAD)] = v.w;
        }
        // W1 chunk (already k-major in global)
        {
            const float4* wsrc = (const float4*)(W1 + (size_t)k0 * TN);
            float4* wdst = (float4*)Ws;
            for (int s = tid; s < BK * TN / 4; s += NTHREADS) wdst[s] = wsrc[s];
        }
        __syncthreads();
#pragma unroll
        for (int k = 0; k < BK; ++k) {
            const u64* ap = (const u64*)&As[k * (TM + PAD) + ty * 8];
            u64 a2[4];
            a2[0] = ap[0]; a2[1] = ap[1]; a2[2] = ap[2]; a2[3] = ap[3];
            float w[8];
            *(float4*)&w[0] = *(const float4*)&Ws[k * TN + tx * 8];
            *(float4*)&w[4] = *(const float4*)&Ws[k * TN + tx * 8 + 4];
            u64 w2[8];
#pragma unroll
            for (int j = 0; j < 8; ++j) w2[j] = pack_dup(w[j]);
#pragma unroll
            for (int i = 0; i < 4; ++i)
#pragma unroll
                for (int j = 0; j < 8; ++j)
                    fma2(acc2[i][j], a2[i], w2[j]);
        }
        __syncthreads();
    }

    // epilogue 1: (+ dsq * W1[256]) + b1, lrelu, store hidden feature-major
    {
        float wlast[8], bb[8];
#pragma unroll
        for (int j = 0; j < 8; ++j) {
            bb[j] = b1[tx * 8 + j];
            if (EDGE) wlast[j] = W1[256 * TN + tx * 8 + j];
        }
#pragma unroll
        for (int i = 0; i < 4; ++i) {
            float d0 = EDGE ? dsq[ty * 8 + 2 * i]     : 0.f;
            float d1 = EDGE ? dsq[ty * 8 + 2 * i + 1] : 0.f;
#pragma unroll
            for (int j = 0; j < 8; ++j) {
                float2 p = unpack2(acc2[i][j]);
                float v0 = p.x + bb[j];
                float v1 = p.y + bb[j];
                if (EDGE) { v0 = fmaf(d0, wlast[j], v0); v1 = fmaf(d1, wlast[j], v1); }
                float* hrow = &Hs[(tx * 8 + j) * (TM + PAD) + ty * 8 + 2 * i];
                hrow[0] = lrelu(v0);
                hrow[1] = lrelu(v1);
            }
        }
    }
    __syncthreads();

    // ---------------- GEMM 2: K = 128 (4 chunks), W2 streamed ---------------
#pragma unroll
    for (int i = 0; i < 4; ++i)
#pragma unroll
        for (int j = 0; j < 8; ++j) acc2[i][j] = 0ULL;

#pragma unroll 1
    for (int kc = 0; kc < 4; ++kc) {
        const int k0 = kc * BK;
        {
            const float4* wsrc = (const float4*)(W2 + (size_t)k0 * TN);
            float4* wdst = (float4*)Ws;
            for (int s = tid; s < BK * TN / 4; s += NTHREADS) wdst[s] = wsrc[s];
        }
        __syncthreads();
#pragma unroll
        for (int k = 0; k < BK; ++k) {
            const u64* ap = (const u64*)&Hs[(k0 + k) * (TM + PAD) + ty * 8];
            u64 a2[4];
            a2[0] = ap[0]; a2[1] = ap[1]; a2[2] = ap[2]; a2[3] = ap[3];
            float w[8];
            *(float4*)&w[0] = *(const float4*)&Ws[k * TN + tx * 8];
            *(float4*)&w[4] = *(const float4*)&Ws[k * TN + tx * 8 + 4];
            u64 w2[8];
#pragma unroll
            for (int j = 0; j < 8; ++j) w2[j] = pack_dup(w[j]);
#pragma unroll
            for (int i = 0; i < 4; ++i)
#pragma unroll
                for (int j = 0; j < 8; ++j)
                    fma2(acc2[i][j], a2[i], w2[j]);
        }
        __syncthreads();
    }

    // epilogue 2
    float bb2[8];
#pragma unroll
    for (int j = 0; j < 8; ++j) bb2[j] = b2[tx * 8 + j];

    if (EDGE) {
        float* mout = g_msg + ((size_t)b * NEDGES + m0) * DIM;
#pragma unroll
        for (int i = 0; i < 4; ++i) {
            float2 u[8];
#pragma unroll
            for (int j = 0; j < 8; ++j) u[j] = unpack2(acc2[i][j]);
            float4 v0, v1;
            // row 2*i
            v0.x = lrelu(u[0].x + bb2[0]); v0.y = lrelu(u[1].x + bb2[1]);
            v0.z = lrelu(u[2].x + bb2[2]); v0.w = lrelu(u[3].x + bb2[3]);
            v1.x = lrelu(u[4].x + bb2[4]); v1.y = lrelu(u[5].x + bb2[5]);
            v1.z = lrelu(u[6].x + bb2[6]); v1.w = lrelu(u[7].x + bb2[7]);
            float* dst0 = mout + (size_t)(ty * 8 + 2 * i) * DIM + tx * 8;
            *(float4*)dst0       = v0;
            *(float4*)(dst0 + 4) = v1;
            // row 2*i+1
            v0.x = lrelu(u[0].y + bb2[0]); v0.y = lrelu(u[1].y + bb2[1]);
            v0.z = lrelu(u[2].y + bb2[2]); v0.w = lrelu(u[3].y + bb2[3]);
            v1.x = lrelu(u[4].y + bb2[4]); v1.y = lrelu(u[5].y + bb2[5]);
            v1.z = lrelu(u[6].y + bb2[6]); v1.w = lrelu(u[7].y + bb2[7]);
            float* dst1 = mout + (size_t)(ty * 8 + 2 * i + 1) * DIM + tx * 8;
            *(float4*)dst1       = v0;
            *(float4*)(dst1 + 4) = v1;
        }
    } else {
        float* hout = g_h + (size_t)b * NNODES * DIM;
#pragma unroll
        for (int i = 0; i < 4; ++i) {
            float2 u[8];
#pragma unroll
            for (int j = 0; j < 8; ++j) u[j] = unpack2(acc2[i][j]);
#pragma unroll
            for (int hhalf = 0; hhalf < 2; ++hhalf) {
                int n = m0 + ty * 8 + 2 * i + hhalf;
                if (n < NNODES) {
                    float* dst = hout + (size_t)n * DIM + tx * 8;
                    float4 o0 = *(float4*)dst;
                    float4 o1 = *(float4*)(dst + 4);
                    float r0 = hhalf ? u[0].y : u[0].x;
                    float r1 = hhalf ? u[1].y : u[1].x;
                    float r2 = hhalf ? u[2].y : u[2].x;
                    float r3 = hhalf ? u[3].y : u[3].x;
                    float r4 = hhalf ? u[4].y : u[4].x;
                    float r5 = hhalf ? u[5].y : u[5].x;
                    float r6 = hhalf ? u[6].y : u[6].x;
                    float r7 = hhalf ? u[7].y : u[7].x;
                    o0.x += lrelu(r0 + bb2[0]); o0.y += lrelu(r1 + bb2[1]);
                    o0.z += lrelu(r2 + bb2[2]); o0.w += lrelu(r3 + bb2[3]);
                    o1.x += lrelu(r4 + bb2[4]); o1.y += lrelu(r5 + bb2[5]);
                    o1.z += lrelu(r6 + bb2[6]); o1.w += lrelu(r7 + bb2[7]);
                    *(float4*)dst       = o0;
                    *(float4*)(dst + 4) = o1;
                }
            }
        }
    }
}

// -------------------- CSR gather-mean aggregation ---------------------------
__global__ void k_aggr() {
    int b = blockIdx.y;
    int n = blockIdx.x * 2 + (threadIdx.x >> 7);
    int j = threadIdx.x & 127;
    const float* mb = g_msg + (size_t)b * NEDGES * DIM;
    int s = g_off[n], t = g_off[n + 1];
    float sum = 0.f;
    for (int i = s; i < t; ++i)
        sum += mb[(size_t)g_perm[i] * DIM + j];
    g_aggr[((size_t)b * NNODES + n) * DIM + j] = sum * g_recip[n];
}

// ----------------------- coord update (tanh GEMV) ---------------------------
__global__ void k_coord(const float* __restrict__ cw, const float* __restrict__ cb) {
    int b    = blockIdx.y;
    int wid  = threadIdx.x >> 5;
    int lane = threadIdx.x & 31;
    int n    = blockIdx.x * 8 + wid;
    if (n >= NNODES) return;
    const float* ar = g_aggr + ((size_t)b * NNODES + n) * DIM;
    float4 a = *(const float4*)(ar + lane * 4);
    float4 w = *(const float4*)(cw + lane * 4);
    float s = a.x * w.x + a.y * w.y + a.z * w.z + a.w * w.w;
#pragma unroll
    for (int o = 16; o; o >>= 1) s += __shfl_xor_sync(0xffffffffu, s, o);
    if (lane == 0) {
        float t = tanhf(s + cb[0]) * 0.1f;
        float* p = &g_pos[((size_t)b * NNODES + n) * 3];
        p[0] += t; p[1] += t; p[2] += t;
    }
}

// ----------------------- mean + projection ----------------------------------
__global__ void k_meanpart() {
    int b = blockIdx.y, p = blockIdx.x, j = threadIdx.x;   // 128 threads
    const float* hb = g_h + (size_t)b * NNODES * DIM;
    const int span = NNODES / NPART;                       // 500
    float s = 0.f;
    int n0 = p * span;
    for (int n = n0; n < n0 + span; ++n) s += hb[(size_t)n * DIM + j];
    g_hpart[(b * NPART + p) * DIM + j] = s;
}

__global__ void k_proj(const float* __restrict__ wp, const float* __restrict__ bp,
                       float* __restrict__ out) {
    __shared__ float hm[BATCH * DIM];
    int tid = threadIdx.x;  // 512
    {
        int b = tid >> 7, j = tid & 127;
        float s = 0.f;
        for (int p = 0; p < NPART; ++p) s += g_hpart[(b * NPART + p) * DIM + j];
        hm[b * DIM + j] = s * (1.0f / NNODES);
    }
    __syncthreads();
    if (tid < BATCH * OUTD) {
        int b = tid / OUTD, o = tid % OUTD;
        float s = bp[o];
        for (int j = 0; j < DIM; ++j) s = fmaf(hm[b * DIM + j], wp[j * OUTD + o], s);
        out[b * OUTD + o] = lrelu(s);
    }
}

// ---------------------------------------------------------------------------
extern "C" void kernel_launch(void* const* d_in, const int* in_sizes, int n_in,
                              void* d_out, int out_size) {
    const float* x   = (const float*)d_in[0];
    const int*   ei  = (const int*)  d_in[1];
    const float* w0  = (const float*)d_in[2];
    const float* b0  = (const float*)d_in[3];
    const float* ew1 = (const float*)d_in[4];
    const float* eb1 = (const float*)d_in[5];
    const float* ew2 = (const float*)d_in[6];
    const float* eb2 = (const float*)d_in[7];
    const float* cw  = (const float*)d_in[8];
    const float* cb  = (const float*)d_in[9];
    const float* nw1 = (const float*)d_in[10];
    const float* nb1 = (const float*)d_in[11];
    const float* nw2 = (const float*)d_in[12];
    const float* nb2 = (const float*)d_in[13];
    const float* wp  = (const float*)d_in[14];
    const float* bp  = (const float*)d_in[15];
    float* out = (float*)d_out;

    const int* row = ei;
    const int* col = ei + NEDGES;

    const int SMEM_MLP =
        (BK * (TM + PAD) + BK * TN + TN * (TM + PAD) + TM) * (int)sizeof(float)
        + 2 * TM * (int)sizeof(int);   // 102,400 bytes

    cudaFuncSetAttribute(mlp_kernel<true>,
                         cudaFuncAttributeMaxDynamicSharedMemorySize, SMEM_MLP);
    cudaFuncSetAttribute(mlp_kernel<false>,
                         cudaFuncAttributeMaxDynamicSharedMemorySize, SMEM_MLP);

    // CSR build (deterministic after per-node sort)
    k_zero_cnt<<<(NNODES + 255) / 256, 256>>>();
    k_count<<<(NEDGES + 255) / 256, 256>>>(col);
    k_scan<<<1, 1024>>>();
    k_fill<<<(NEDGES + 255) / 256, 256>>>(col);
    k_sort<<<(NNODES + 127) / 128, 128>>>();

    // init
    k_init_pos<<<(BATCH * NNODES * 3 + 255) / 256, 256>>>(x);
    k_h0<<<(BATCH * NNODES * DIM + 255) / 256, 256>>>(w0, b0);

    for (int l = 0; l < NLAYERS; ++l) {
        mlp_kernel<true><<<dim3(NEDGES / TM, BATCH), NTHREADS, SMEM_MLP>>>(
            row, col,
            ew1 + (size_t)l * 257 * DIM, eb1 + l * DIM,
            ew2 + (size_t)l * DIM * DIM, eb2 + l * DIM);
        k_aggr<<<dim3(NNODES / 2, BATCH), 256>>>();
        k_coord<<<dim3(NNODES / 8, BATCH), 256>>>(cw + l * DIM, cb + l);
        mlp_kernel<false><<<dim3((NNODES + TM - 1) / TM, BATCH), NTHREADS, SMEM_MLP>>>(
            row, col,
            nw1 + (size_t)l * 2 * DIM * DIM, nb1 + l * DIM,
            nw2 + (size_t)l * DIM * DIM, nb2 + l * DIM);
    }

    k_meanpart<<<dim3(NPART, BATCH), 128>>>();
    k_proj<<<1, 512>>>(wp, bp, out);
}

// round 6
// speedup vs baseline: 2.0446x; 2.0446x over previous
#include <cuda_runtime.h>
#include <math.h>
#include <stdint.h>

// ---------------------------------------------------------------------------
// EGNN  B=4, N=10000, E=160000, D=128, OUT=64, L=4
// R5: GEMM mainloops on tensor core via mma.sync m16n8k8 tf32, 3xTF32 split
//     (hi*hi + hi*lo + lo*hi, fp32 accum) -> fp32-grade precision.
// ---------------------------------------------------------------------------
#define BATCH    4
#define NNODES   10000
#define NEDGES   160000
#define DIM      128
#define OUTD     64
#define NLAYERS  4
#define NEG      0.01f

#define TM       128     // edges/nodes per CTA tile
#define TN       128     // output features
#define BK       32      // K chunk
#define PAD      4
#define STR      (TM + PAD)   // 132, shared stride for A/W/H tiles
#define NTHREADS 256
#define NPART    20      // mean partials (deterministic)

// ------------------------- device scratch (no mallocs) ---------------------
__device__ float g_pos[BATCH * NNODES * 3];
__device__ float g_h[(size_t)BATCH * NNODES * DIM];
__device__ float g_aggr[(size_t)BATCH * NNODES * DIM];
__device__ float g_msg[(size_t)BATCH * NEDGES * DIM];
__device__ int   g_cnt[NNODES];
__device__ float g_recip[NNODES];
__device__ int   g_off[NNODES + 1];
__device__ int   g_cursor[NNODES];
__device__ int   g_perm[NEDGES];
__device__ float g_hpart[BATCH * NPART * DIM];

__device__ __forceinline__ float lrelu(float x) { return x > 0.f ? x : NEG * x; }

// ---- tf32 split + mma helpers ---------------------------------------------
__device__ __forceinline__ void split_tf32(float x, uint32_t& hi, uint32_t& lo) {
    asm("cvt.rna.tf32.f32 %0, %1;" : "=r"(hi) : "f"(x));
    float l = x - __uint_as_float(hi);
    asm("cvt.rna.tf32.f32 %0, %1;" : "=r"(lo) : "f"(l));
}

__device__ __forceinline__ void mma8(float* c, const uint32_t* a, const uint32_t* b) {
    asm("mma.sync.aligned.m16n8k8.row.col.f32.tf32.tf32.f32 "
        "{%0,%1,%2,%3}, {%4,%5,%6,%7}, {%8,%9}, {%0,%1,%2,%3};"
        : "+f"(c[0]), "+f"(c[1]), "+f"(c[2]), "+f"(c[3])
        : "r"(a[0]), "r"(a[1]), "r"(a[2]), "r"(a[3]), "r"(b[0]), "r"(b[1]));
}

// ------------------------------ CSR build ----------------------------------
__global__ void k_zero_cnt() {
    int n = blockIdx.x * blockDim.x + threadIdx.x;
    if (n < NNODES) g_cnt[n] = 0;
}

__global__ void k_count(const int* __restrict__ col) {
    int e = blockIdx.x * blockDim.x + threadIdx.x;
    if (e < NEDGES) atomicAdd(&g_cnt[col[e]], 1);
}

// single-block inclusive scan over N=10000 (10 chunks of 1024)
__global__ void k_scan() {
    __shared__ int ss[1024];
    int tid = threadIdx.x;
    int running = 0;
    for (int c = 0; c < 10; ++c) {
        int n = c * 1024 + tid;
        int v = (n < NNODES) ? g_cnt[n] : 0;
        ss[tid] = v;
        __syncthreads();
        for (int d = 1; d < 1024; d <<= 1) {
            int t = (tid >= d) ? ss[tid - d] : 0;
            __syncthreads();
            ss[tid] += t;
            __syncthreads();
        }
        int incl = ss[tid];
        if (n < NNODES) {
            g_off[n + 1]  = running + incl;
            g_cursor[n]   = running + incl - v;   // exclusive prefix
            g_recip[n]    = 1.0f / fmaxf((float)v, 1.0f);
        }
        if (c == 0 && tid == 0) g_off[0] = 0;
        int tot = ss[1023];
        __syncthreads();      // all reads done before next chunk overwrites ss
        running += tot;
    }
}

__global__ void k_fill(const int* __restrict__ col) {
    int e = blockIdx.x * blockDim.x + threadIdx.x;
    if (e < NEDGES) {
        int p = atomicAdd(&g_cursor[col[e]], 1);
        g_perm[p] = e;
    }
}

// sort each node's edge list ascending -> deterministic summation order
__global__ void k_sort() {
    int n = blockIdx.x * blockDim.x + threadIdx.x;
    if (n >= NNODES) return;
    int s = g_off[n], t = g_off[n + 1];
    for (int i = s + 1; i < t; ++i) {
        int v = g_perm[i];
        int j = i - 1;
        while (j >= s && g_perm[j] > v) { g_perm[j + 1] = g_perm[j]; --j; }
        g_perm[j + 1] = v;
    }
}

// ------------------------------ init ---------------------------------------
__global__ void k_init_pos(const float* __restrict__ x) {
    int i = blockIdx.x * blockDim.x + threadIdx.x;
    if (i < BATCH * NNODES * 3) g_pos[i] = x[i];  // identical flat layout
}

__global__ void k_h0(const float* __restrict__ w0, const float* __restrict__ b0) {
    int i = blockIdx.x * blockDim.x + threadIdx.x;
    if (i >= BATCH * NNODES * DIM) return;
    int j  = i & (DIM - 1);
    int bn = i >> 7;
    const float* p = &g_pos[bn * 3];
    float v = b0[j] + p[0] * w0[j] + p[1] * w0[DIM + j] + p[2] * w0[2 * DIM + j];
    g_h[i] = lrelu(v);
}

// --------------------- fused 2-layer MLP GEMM kernel ------------------------
// EDGE=true : A row e = [h[row[e]], h[col[e]], dist_sq] (K=257, last col special)
//             out -> g_msg
// EDGE=false: A row n = [h[n], aggr[n]] (K=256), out -> g_h += lrelu(...)
// CTA tile 128x128, 8 warps, warp tile 32x64, tensor-core mainloop
// (mma.sync m16n8k8 tf32, 3-pass split). Hidden kept in SMEM feature-major.
template <bool EDGE>
__global__ void __launch_bounds__(NTHREADS)
mlp_kernel(const int* __restrict__ row, const int* __restrict__ col,
           const float* __restrict__ W1, const float* __restrict__ b1,
           const float* __restrict__ W2, const float* __restrict__ b2)
{
    extern __shared__ float smem[];
    float* As  = smem;                  // [BK][STR]   k-major A chunk
    float* Ws  = As + BK * STR;         // [BK][STR]   k-major W chunk (padded)
    float* Hs  = Ws + BK * STR;         // [TN][STR]   hidden, feature-major
    float* dsq = Hs + TN * STR;         // [TM]
    int*   nid = (int*)(dsq + TM);      // [2*TM]

    const int b    = blockIdx.y;
    const int m0   = blockIdx.x * TM;
    const int tid  = threadIdx.x;
    const int wid  = tid >> 5;
    const int lane = tid & 31;
    const int gid  = lane >> 2;   // 0..7
    const int tig  = lane & 3;    // 0..3
    const int wm   = (wid & 3) * 32;    // warp M origin (4 warps over 128)
    const int wn   = (wid >> 2) * 64;   // warp N origin (2 warps over 128)

    const float* hb = g_h    + (size_t)b * NNODES * DIM;
    const float* ab = g_aggr + (size_t)b * NNODES * DIM;

    if (EDGE) {
        for (int i = tid; i < TM; i += NTHREADS) {
            int e = m0 + i;
            int r = row[e], c = col[e];
            nid[i]      = r;
            nid[TM + i] = c;
            const float* pr = &g_pos[((size_t)b * NNODES + r) * 3];
            const float* pc = &g_pos[((size_t)b * NNODES + c) * 3];
            float dx = pr[0] - pc[0], dy = pr[1] - pc[1], dz = pr[2] - pc[2];
            dsq[i] = dx * dx + dy * dy + dz * dz;
        }
        __syncthreads();
    }

    float acc[2][8][4];
#pragma unroll
    for (int mi = 0; mi < 2; ++mi)
#pragma unroll
        for (int ni = 0; ni < 8; ++ni)
#pragma unroll
            for (int c = 0; c < 4; ++c) acc[mi][ni][c] = 0.f;

    // ---------------- GEMM 1: K = 256 (8 chunks); +dsq column for EDGE ------
#pragma unroll 1
    for (int kc = 0; kc < 8; ++kc) {
        const int k0 = kc * BK;
        // gathered A tile (k-major in SMEM)
        for (int s = tid; s < TM * 8; s += NTHREADS) {
            int ei = s >> 3, q = s & 7;
            const float* src;
            if (EDGE) {
                int node = (kc < 4) ? nid[ei] : nid[TM + ei];
                int kh   = (kc < 4) ? k0 : (k0 - DIM);
                src = hb + (size_t)node * DIM + kh + q * 4;
            } else {
                int node = m0 + ei;
                if (node >= NNODES) node = NNODES - 1;
                src = (kc < 4) ? (hb + (size_t)node * DIM + k0 + q * 4)
                               : (ab + (size_t)node * DIM + (k0 - DIM) + q * 4);
            }
            float4 v = *(const float4*)src;
            float* dst = &As[(q * 4) * STR + ei];
            dst[0]       = v.x;
            dst[STR]     = v.y;
            dst[2 * STR] = v.z;
            dst[3 * STR] = v.w;
        }
        // W1 chunk (k-major in global, padded stride in SMEM)
        for (int s = tid; s < BK * TN / 4; s += NTHREADS) {
            int r = s >> 5, c4 = s & 31;
            *(float4*)&Ws[r * STR + c4 * 4] =
                ((const float4*)(W1 + (size_t)k0 * TN))[s];
        }
        __syncthreads();
#pragma unroll
        for (int k8 = 0; k8 < 4; ++k8) {
            const int ks = k8 * 8;
            uint32_t ah[2][4], al[2][4];
#pragma unroll
            for (int mi = 0; mi < 2; ++mi)
#pragma unroll
                for (int r = 0; r < 4; ++r) {
                    int kk = ks + tig + ((r >> 1) << 2);
                    int mm = wm + mi * 16 + gid + ((r & 1) << 3);
                    split_tf32(As[kk * STR + mm], ah[mi][r], al[mi][r]);
                }
#pragma unroll
            for (int h = 0; h < 2; ++h) {
                uint32_t bh[4][2], bl[4][2];
#pragma unroll
                for (int ni = 0; ni < 4; ++ni) {
                    int nn = wn + (h * 4 + ni) * 8 + gid;
                    split_tf32(Ws[(ks + tig) * STR + nn],     bh[ni][0], bl[ni][0]);
                    split_tf32(Ws[(ks + tig + 4) * STR + nn], bh[ni][1], bl[ni][1]);
                }
#pragma unroll
                for (int mi = 0; mi < 2; ++mi)
#pragma unroll
                    for (int ni = 0; ni < 4; ++ni) {
                        float* c = acc[mi][h * 4 + ni];
                        mma8(c, ah[mi], bh[ni]);
                        mma8(c, ah[mi], bl[ni]);
                        mma8(c, al[mi], bh[ni]);
                    }
            }
        }
        __syncthreads();
    }

    // epilogue 1: (+ dsq * W1[256]) + b1, lrelu, store hidden feature-major
    {
        float bb0[8], bb1[8], wl0[8], wl1[8];
#pragma unroll
        for (int ni = 0; ni < 8; ++ni) {
            int n0 = wn + ni * 8 + tig * 2;
            bb0[ni] = b1[n0];
            bb1[ni] = b1[n0 + 1];
            if (EDGE) { wl0[ni] = W1[256 * TN + n0]; wl1[ni] = W1[256 * TN + n0 + 1]; }
        }
        float dA[2] = {0.f, 0.f}, dB[2] = {0.f, 0.f};
        if (EDGE) {
#pragma unroll
            for (int mi = 0; mi < 2; ++mi) {
                dA[mi] = dsq[wm + mi * 16 + gid];
                dB[mi] = dsq[wm + mi * 16 + gid + 8];
            }
        }
#pragma unroll
        for (int mi = 0; mi < 2; ++mi) {
            int mA = wm + mi * 16 + gid, mB = mA + 8;
#pragma unroll
            for (int ni = 0; ni < 8; ++ni) {
                int n0 = wn + ni * 8 + tig * 2;
                float v0 = acc[mi][ni][0] + bb0[ni];
                float v1 = acc[mi][ni][1] + bb1[ni];
                float v2 = acc[mi][ni][2] + bb0[ni];
                float v3 = acc[mi][ni][3] + bb1[ni];
                if (EDGE) {
                    v0 = fmaf(dA[mi], wl0[ni], v0); v1 = fmaf(dA[mi], wl1[ni], v1);
                    v2 = fmaf(dB[mi], wl0[ni], v2); v3 = fmaf(dB[mi], wl1[ni], v3);
                }
                Hs[n0 * STR + mA]       = lrelu(v0);
                Hs[(n0 + 1) * STR + mA] = lrelu(v1);
                Hs[n0 * STR + mB]       = lrelu(v2);
                Hs[(n0 + 1) * STR + mB] = lrelu(v3);
            }
        }
    }
    __syncthreads();

    // ---------------- GEMM 2: K = 128 (4 chunks), W2 streamed ---------------
#pragma unroll
    for (int mi = 0; mi < 2; ++mi)
#pragma unroll
        for (int ni = 0; ni < 8; ++ni)
#pragma unroll
            for (int c = 0; c < 4; ++c) acc[mi][ni][c] = 0.f;

#pragma unroll 1
    for (int kc = 0; kc < 4; ++kc) {
        const int k0 = kc * BK;
        for (int s = tid; s < BK * TN / 4; s += NTHREADS) {
            int r = s >> 5, c4 = s & 31;
            *(float4*)&Ws[r * STR + c4 * 4] =
                ((const float4*)(W2 + (size_t)k0 * TN))[s];
        }
        __syncthreads();
        const float* Asrc = Hs + k0 * STR;
#pragma unroll
        for (int k8 = 0; k8 < 4; ++k8) {
            const int ks = k8 * 8;
            uint32_t ah[2][4], al[2][4];
#pragma unroll
            for (int mi = 0; mi < 2; ++mi)
#pragma unroll
                for (int r = 0; r < 4; ++r) {
                    int kk = ks + tig + ((r >> 1) << 2);
                    int mm = wm + mi * 16 + gid + ((r & 1) << 3);
                    split_tf32(Asrc[kk * STR + mm], ah[mi][r], al[mi][r]);
                }
#pragma unroll
            for (int h = 0; h < 2; ++h) {
                uint32_t bh[4][2], bl[4][2];
#pragma unroll
                for (int ni = 0; ni < 4; ++ni) {
                    int nn = wn + (h * 4 + ni) * 8 + gid;
                    split_tf32(Ws[(ks + tig) * STR + nn],     bh[ni][0], bl[ni][0]);
                    split_tf32(Ws[(ks + tig + 4) * STR + nn], bh[ni][1], bl[ni][1]);
                }
#pragma unroll
                for (int mi = 0; mi < 2; ++mi)
#pragma unroll
                    for (int ni = 0; ni < 4; ++ni) {
                        float* c = acc[mi][h * 4 + ni];
                        mma8(c, ah[mi], bh[ni]);
                        mma8(c, ah[mi], bl[ni]);
                        mma8(c, al[mi], bh[ni]);
                    }
            }
        }
        __syncthreads();
    }

    // epilogue 2
    {
        float bb0[8], bb1[8];
#pragma unroll
        for (int ni = 0; ni < 8; ++ni) {
            int n0 = wn + ni * 8 + tig * 2;
            bb0[ni] = b2[n0];
            bb1[ni] = b2[n0 + 1];
        }
        if (EDGE) {
            float* mout = g_msg + ((size_t)b * NEDGES + m0) * DIM;
#pragma unroll
            for (int mi = 0; mi < 2; ++mi) {
                int mA = wm + mi * 16 + gid, mB = mA + 8;
#pragma unroll
                for (int ni = 0; ni < 8; ++ni) {
                    int n0 = wn + ni * 8 + tig * 2;
                    float2 vA = make_float2(lrelu(acc[mi][ni][0] + bb0[ni]),
                                            lrelu(acc[mi][ni][1] + bb1[ni]));
                    float2 vB = make_float2(lrelu(acc[mi][ni][2] + bb0[ni]),
                                            lrelu(acc[mi][ni][3] + bb1[ni]));
                    *(float2*)(mout + (size_t)mA * DIM + n0) = vA;
                    *(float2*)(mout + (size_t)mB * DIM + n0) = vB;
                }
            }
        } else {
            float* hout = g_h + (size_t)b * NNODES * DIM;
#pragma unroll
            for (int mi = 0; mi < 2; ++mi) {
                int mA = wm + mi * 16 + gid, mB = mA + 8;
                int nA = m0 + mA, nB = m0 + mB;
#pragma unroll
                for (int ni = 0; ni < 8; ++ni) {
                    int n0 = wn + ni * 8 + tig * 2;
                    if (nA < NNODES) {
                        float2* p = (float2*)(hout + (size_t)nA * DIM + n0);
                        float2 o = *p;
                        o.x += lrelu(acc[mi][ni][0] + bb0[ni]);
                        o.y += lrelu(acc[mi][ni][1] + bb1[ni]);
                        *p = o;
                    }
                    if (nB < NNODES) {
                        float2* p = (float2*)(hout + (size_t)nB * DIM + n0);
                        float2 o = *p;
                        o.x += lrelu(acc[mi][ni][2] + bb0[ni]);
                        o.y += lrelu(acc[mi][ni][3] + bb1[ni]);
                        *p = o;
                    }
                }
            }
        }
    }
}

// -------------------- CSR gather-mean aggregation ---------------------------
__global__ void k_aggr() {
    int b = blockIdx.y;
    int n = blockIdx.x * 2 + (threadIdx.x >> 7);
    int j = threadIdx.x & 127;
    const float* mb = g_msg + (size_t)b * NEDGES * DIM;
    int s = g_off[n], t = g_off[n + 1];
    float sum = 0.f;
    for (int i = s; i < t; ++i)
        sum += mb[(size_t)g_perm[i] * DIM + j];
    g_aggr[((size_t)b * NNODES + n) * DIM + j] = sum * g_recip[n];
}

// ----------------------- coord update (tanh GEMV) ---------------------------
__global__ void k_coord(const float* __restrict__ cw, const float* __restrict__ cb) {
    int b    = blockIdx.y;
    int wid  = threadIdx.x >> 5;
    int lane = threadIdx.x & 31;
    int n    = blockIdx.x * 8 + wid;
    if (n >= NNODES) return;
    const float* ar = g_aggr + ((size_t)b * NNODES + n) * DIM;
    float4 a = *(const float4*)(ar + lane * 4);
    float4 w = *(const float4*)(cw + lane * 4);
    float s = a.x * w.x + a.y * w.y + a.z * w.z + a.w * w.w;
#pragma unroll
    for (int o = 16; o; o >>= 1) s += __shfl_xor_sync(0xffffffffu, s, o);
    if (lane == 0) {
        float t = tanhf(s + cb[0]) * 0.1f;
        float* p = &g_pos[((size_t)b * NNODES + n) * 3];
        p[0] += t; p[1] += t; p[2] += t;
    }
}

// ----------------------- mean + projection ----------------------------------
__global__ void k_meanpart() {
    int b = blockIdx.y, p = blockIdx.x, j = threadIdx.x;   // 128 threads
    const float* hb = g_h + (size_t)b * NNODES * DIM;
    const int span = NNODES / NPART;                       // 500
    float s = 0.f;
    int n0 = p * span;
    for (int n = n0; n < n0 + span; ++n) s += hb[(size_t)n * DIM + j];
    g_hpart[(b * NPART + p) * DIM + j] = s;
}

__global__ void k_proj(const float* __restrict__ wp, const float* __restrict__ bp,
                       float* __restrict__ out) {
    __shared__ float hm[BATCH * DIM];
    int tid = threadIdx.x;  // 512
    {
        int b = tid >> 7, j = tid & 127;
        float s = 0.f;
        for (int p = 0; p < NPART; ++p) s += g_hpart[(b * NPART + p) * DIM + j];
        hm[b * DIM + j] = s * (1.0f / NNODES);
    }
    __syncthreads();
    if (tid < BATCH * OUTD) {
        int b = tid / OUTD, o = tid % OUTD;
        float s = bp[o];
        for (int j = 0; j < DIM; ++j) s = fmaf(hm[b * DIM + j], wp[j * OUTD + o], s);
        out[b * OUTD + o] = lrelu(s);
    }
}

// ---------------------------------------------------------------------------
extern "C" void kernel_launch(void* const* d_in, const int* in_sizes, int n_in,
                              void* d_out, int out_size) {
    const float* x   = (const float*)d_in[0];
    const int*   ei  = (const int*)  d_in[1];
    const float* w0  = (const float*)d_in[2];
    const float* b0  = (const float*)d_in[3];
    const float* ew1 = (const float*)d_in[4];
    const float* eb1 = (const float*)d_in[5];
    const float* ew2 = (const float*)d_in[6];
    const float* eb2 = (const float*)d_in[7];
    const float* cw  = (const float*)d_in[8];
    const float* cb  = (const float*)d_in[9];
    const float* nw1 = (const float*)d_in[10];
    const float* nb1 = (const float*)d_in[11];
    const float* nw2 = (const float*)d_in[12];
    const float* nb2 = (const float*)d_in[13];
    const float* wp  = (const float*)d_in[14];
    const float* bp  = (const float*)d_in[15];
    float* out = (float*)d_out;

    const int* row = ei;
    const int* col = ei + NEDGES;

    const int SMEM_MLP =
        (BK * STR + BK * STR + TN * STR + TM) * (int)sizeof(float)
        + 2 * TM * (int)sizeof(int);

    cudaFuncSetAttribute(mlp_kernel<true>,
                         cudaFuncAttributeMaxDynamicSharedMemorySize, SMEM_MLP);
    cudaFuncSetAttribute(mlp_kernel<false>,
                         cudaFuncAttributeMaxDynamicSharedMemorySize, SMEM_MLP);

    // CSR build (deterministic after per-node sort)
    k_zero_cnt<<<(NNODES + 255) / 256, 256>>>();
    k_count<<<(NEDGES + 255) / 256, 256>>>(col);
    k_scan<<<1, 1024>>>();
    k_fill<<<(NEDGES + 255) / 256, 256>>>(col);
    k_sort<<<(NNODES + 127) / 128, 128>>>();

    // init
    k_init_pos<<<(BATCH * NNODES * 3 + 255) / 256, 256>>>(x);
    k_h0<<<(BATCH * NNODES * DIM + 255) / 256, 256>>>(w0, b0);

    for (int l = 0; l < NLAYERS; ++l) {
        mlp_kernel<true><<<dim3(NEDGES / TM, BATCH), NTHREADS, SMEM_MLP>>>(
            row, col,
            ew1 + (size_t)l * 257 * DIM, eb1 + l * DIM,
            ew2 + (size_t)l * DIM * DIM, eb2 + l * DIM);
        k_aggr<<<dim3(NNODES / 2, BATCH), 256>>>();
        k_coord<<<dim3(NNODES / 8, BATCH), 256>>>(cw + l * DIM, cb + l);
        mlp_kernel<false><<<dim3((NNODES + TM - 1) / TM, BATCH), NTHREADS, SMEM_MLP>>>(
            row, col,
            nw1 + (size_t)l * 2 * DIM * DIM, nb1 + l * DIM,
            nw2 + (size_t)l * DIM * DIM, nb2 + l * DIM);
    }

    k_meanpart<<<dim3(NPART, BATCH), 128>>>();
    k_proj<<<1, 512>>>(wp, bp, out);
}